// round 5
// baseline (speedup 1.0000x reference)
#include <cuda_runtime.h>
#include <math.h>

#define Bb 16
#define Tt 1024
#define Dd 512
#define Vv 5000
#define Lc 128
#define Mm (Bb*Tt)          // 16384
#define Sz (2*Lc+1)         // 257
#define NEGV (-1e30f)
#define NLAB 129            // blank + 128 labels

// scratch (static device allocations only — no cudaMalloc allowed)
__device__ float g_lse[Mm];
__device__ float g_lab[(size_t)Bb*Tt*NLAB];
__device__ float g_loss[Bb];

// ---------------------------------------------------------------------------
// Kernel A: fused GEMM (H[16384x512] x W[512x5000]) + row-wise online LSE.
// Tile: BM=64 rows, BN=128 cols, BK=16. 256 threads; thread = (ty,tx) 16x16,
// microtile 4 rows x 8 cols. Running (max, sumexp) per row-slice in registers,
// butterfly-combined over the 16 tx lanes at the end.
// ---------------------------------------------------------------------------
__global__ __launch_bounds__(256, 2) void lse_kernel(
    const float* __restrict__ hs, const float* __restrict__ W,
    const float* __restrict__ bias)
{
    __shared__ float sH[16][64];
    __shared__ float sW[16][128];
    __shared__ float sB[128];

    const int m0  = blockIdx.x * 64;
    const int tid = threadIdx.x;
    const int ty  = tid >> 4;     // 0..15 -> rows ty*4..+3
    const int tx  = tid & 15;     // 0..15 -> cols tx*8..+7

    float Mr[4], Sr[4];
#pragma unroll
    for (int i = 0; i < 4; i++) { Mr[i] = NEGV; Sr[i] = 0.f; }

    for (int nt = 0; nt < 40; nt++) {
        const int n0 = nt * 128;
        __syncthreads();                 // protect sB/smem from previous tile readers
        if (tid < 32) {
            int n = n0 + tid * 4;
            float4 bv = (n + 3 < Vv) ? *(const float4*)(bias + n)
                                     : make_float4(0.f, 0.f, 0.f, 0.f);
            *(float4*)(&sB[tid * 4]) = bv;
        }

        float acc[4][8];
#pragma unroll
        for (int i = 0; i < 4; i++)
#pragma unroll
            for (int j = 0; j < 8; j++) acc[i][j] = 0.f;

        for (int kt = 0; kt < 32; kt++) {
            const int k0 = kt * 16;
            // H tile: 64x16 = 256 float4, one per thread (store transposed)
            {
                int mrow = tid >> 2, k4 = tid & 3;
                float4 h = *(const float4*)(hs + (size_t)(m0 + mrow) * Dd + k0 + k4 * 4);
                sH[k4 * 4 + 0][mrow] = h.x;
                sH[k4 * 4 + 1][mrow] = h.y;
                sH[k4 * 4 + 2][mrow] = h.z;
                sH[k4 * 4 + 3][mrow] = h.w;
            }
            // W tile: 16x128 = 512 float4, two per thread
#pragma unroll
            for (int q = 0; q < 2; q++) {
                int s  = tid * 2 + q;
                int kr = s >> 5, n4 = s & 31;
                int n  = n0 + n4 * 4;
                float4 wv = (n + 3 < Vv)
                    ? *(const float4*)(W + (size_t)(k0 + kr) * Vv + n)
                    : make_float4(0.f, 0.f, 0.f, 0.f);
                *(float4*)(&sW[kr][n4 * 4]) = wv;
            }
            __syncthreads();
#pragma unroll
            for (int kk = 0; kk < 16; kk++) {
                float a[4], w[8];
#pragma unroll
                for (int i = 0; i < 4; i++) a[i] = sH[kk][ty * 4 + i];
#pragma unroll
                for (int j = 0; j < 8; j++) w[j] = sW[kk][tx * 8 + j];
#pragma unroll
                for (int i = 0; i < 4; i++)
#pragma unroll
                    for (int j = 0; j < 8; j++)
                        acc[i][j] = fmaf(a[i], w[j], acc[i][j]);
            }
            __syncthreads();
        }

        // online (max,sumexp) update for this N tile
#pragma unroll
        for (int i = 0; i < 4; i++) {
            float v[8], vmax = NEGV;
#pragma unroll
            for (int j = 0; j < 8; j++) {
                int n = n0 + tx * 8 + j;
                v[j] = (n < Vv) ? acc[i][j] + sB[tx * 8 + j] : NEGV;
                vmax = fmaxf(vmax, v[j]);
            }
            float newM = fmaxf(Mr[i], vmax);
            float s = Sr[i] * __expf(Mr[i] - newM);
#pragma unroll
            for (int j = 0; j < 8; j++) s += __expf(v[j] - newM);
            Mr[i] = newM; Sr[i] = s;
        }
    }

    // butterfly over the 16 tx lanes (lanes differ only in low 4 bits)
#pragma unroll
    for (int i = 0; i < 4; i++) {
        float m = Mr[i], s = Sr[i];
#pragma unroll
        for (int off = 1; off < 16; off <<= 1) {
            float om = __shfl_xor_sync(0xffffffffu, m, off);
            float os = __shfl_xor_sync(0xffffffffu, s, off);
            float nm = fmaxf(m, om);
            s = s * __expf(m - nm) + os * __expf(om - nm);
            m = nm;
        }
        if (tx == 0) g_lse[m0 + ty * 4 + i] = m + logf(s);
    }
}

// ---------------------------------------------------------------------------
// Kernel B: gathered-label logits -> log-probs.
// lab_logp[b][t][j] = h[b,t] . W[:, v_j] + bias[v_j] - lse[b,t]
//   j=0 -> blank (v=0), j=1..128 -> ys_pad[b][j-1]
// Grid: (T/64, B). Tile 64 rows x 129 cols (padded to 144), BK=16.
// ---------------------------------------------------------------------------
__global__ __launch_bounds__(256) void lab_kernel(
    const float* __restrict__ hs, const float* __restrict__ W,
    const float* __restrict__ bias, const int* __restrict__ ys)
{
    __shared__ float sH[16][64];
    __shared__ float sWg[16][144];
    __shared__ float sBg[144];
    __shared__ int   sV[144];

    const int b   = blockIdx.y;
    const int t0  = blockIdx.x * 64;
    const int tid = threadIdx.x;
    const int ty  = tid >> 4;   // rows ty*4..+3
    const int tx  = tid & 15;   // cols tx + 16*c

    if (tid < 144) {
        int v = 0;
        if (tid >= 1 && tid < NLAB) v = ys[b * Lc + tid - 1];
        sV[tid]  = v;
        sBg[tid] = (tid < NLAB) ? bias[v] : 0.f;
    }
    __syncthreads();

    float acc[4][9];
#pragma unroll
    for (int i = 0; i < 4; i++)
#pragma unroll
        for (int c = 0; c < 9; c++) acc[i][c] = 0.f;

    for (int kt = 0; kt < 32; kt++) {
        const int k0 = kt * 16;
        {
            int mrow = tid >> 2, k4 = tid & 3;
            float4 h = *(const float4*)(hs + (size_t)(b * Tt + t0 + mrow) * Dd + k0 + k4 * 4);
            sH[k4 * 4 + 0][mrow] = h.x;
            sH[k4 * 4 + 1][mrow] = h.y;
            sH[k4 * 4 + 2][mrow] = h.z;
            sH[k4 * 4 + 3][mrow] = h.w;
        }
        for (int idx = tid; idx < 16 * 144; idx += 256) {
            int kr = idx / 144, j = idx % 144;
            sWg[kr][j] = (j < NLAB) ? W[(size_t)(k0 + kr) * Vv + sV[j]] : 0.f;
        }
        __syncthreads();
#pragma unroll
        for (int kk = 0; kk < 16; kk++) {
            float a[4], w[9];
#pragma unroll
            for (int i = 0; i < 4; i++) a[i] = sH[kk][ty * 4 + i];
#pragma unroll
            for (int c = 0; c < 9; c++) w[c] = sWg[kk][tx + 16 * c];
#pragma unroll
            for (int i = 0; i < 4; i++)
#pragma unroll
                for (int c = 0; c < 9; c++)
                    acc[i][c] = fmaf(a[i], w[c], acc[i][c]);
        }
        __syncthreads();
    }

#pragma unroll
    for (int i = 0; i < 4; i++) {
        int m = b * Tt + t0 + ty * 4 + i;
        float lse = g_lse[m];
#pragma unroll
        for (int c = 0; c < 9; c++) {
            int j = tx + 16 * c;
            if (j < NLAB)
                g_lab[(size_t)m * NLAB + j] = acc[i][c] + sBg[j] - lse;
        }
    }
}

// ---------------------------------------------------------------------------
// Kernel C: CTC alpha recursion. One block per batch, thread s owns state s.
// ---------------------------------------------------------------------------
__global__ __launch_bounds__(288) void ctc_kernel(
    const int* __restrict__ hlens, const int* __restrict__ ys,
    const int* __restrict__ yslens)
{
    __shared__ float A0[Sz];
    __shared__ float A1[Sz];

    const int b   = blockIdx.x;
    const int tid = threadIdx.x;
    const int hlen = hlens[b];
    const float* lp = g_lab + (size_t)b * Tt * NLAB;

    int  labj  = 0;
    bool allow = false;
    if (tid < Sz) {
        if (tid & 1) {
            labj = (tid + 1) >> 1;                 // 1..128
            int y     = ys[b * Lc + labj - 1];
            int yprev = (tid >= 3) ? ys[b * Lc + labj - 2] : -1;
            allow = (y != yprev);
        }
        float a0 = NEGV;
        if (tid == 0) a0 = lp[0];        // t=0, blank
        if (tid == 1) a0 = lp[1];        // t=0, first label
        A0[tid] = a0;
    }
    __syncthreads();

    float lp_cur = 0.f, lp_nxt = 0.f;
    if (tid < Sz) lp_cur = lp[(size_t)1 * NLAB + labj];

    float* cur = A0;
    float* nxt = A1;
    for (int t = 1; t < hlen; t++) {
        if (tid < Sz) {
            int tl = (t + 1 < Tt) ? (t + 1) : (Tt - 1);
            lp_nxt = lp[(size_t)tl * NLAB + labj];     // prefetch
            float a1 = cur[tid];
            float a2 = (tid >= 1) ? cur[tid - 1] : NEGV;
            float a3 = (allow && tid >= 2) ? cur[tid - 2] : NEGV;
            float m  = fmaxf(fmaxf(a1, a2), a3);
            m = fmaxf(m, NEGV);
            float s = __expf(a1 - m) + __expf(a2 - m) + __expf(a3 - m);
            nxt[tid] = m + __logf(s) + lp_cur;
        }
        __syncthreads();
        lp_cur = lp_nxt;
        float* tmp = cur; cur = nxt; nxt = tmp;
    }

    if (tid == 0) {
        int yl = yslens[b];
        int i1 = 2 * yl;
        int i2 = (i1 - 1 > 0) ? (i1 - 1) : 0;
        float a = cur[i1], c2 = cur[i2];
        float m = fmaxf(a, c2);
        float ll = m + __logf(__expf(a - m) + __expf(c2 - m));
        float loss = -ll;
        if (!isfinite(loss) || loss >= 1e29f) loss = 0.f;
        g_loss[b] = loss;
    }
}

// ---------------------------------------------------------------------------
// Kernel D: final reduction + normalization.
// ---------------------------------------------------------------------------
__global__ void final_kernel(const int* __restrict__ yslens, float* __restrict__ out)
{
    if (threadIdx.x == 0) {
        float s = 0.f;
        int tl = 0;
        for (int i = 0; i < Bb; i++) { s += g_loss[i]; tl += yslens[i]; }
        out[0] = s / (float)tl;
    }
}

extern "C" void kernel_launch(void* const* d_in, const int* in_sizes, int n_in,
                              void* d_out, int out_size)
{
    const float* hs     = (const float*)d_in[0];
    const int*   hlens  = (const int*)  d_in[1];
    const int*   ys     = (const int*)  d_in[2];
    const int*   yslens = (const int*)  d_in[3];
    const float* W      = (const float*)d_in[4];
    const float* bias   = (const float*)d_in[5];

    lse_kernel<<<Mm / 64, 256>>>(hs, W, bias);
    dim3 gb(Tt / 64, Bb);
    lab_kernel<<<gb, 256>>>(hs, W, bias, ys);
    ctc_kernel<<<Bb, 288>>>(hlens, ys, yslens);
    final_kernel<<<1, 32>>>(yslens, (float*)d_out);
}

// round 9
// speedup vs baseline: 5.2240x; 5.2240x over previous
#include <cuda_runtime.h>
#include <cuda_bf16.h>
#include <cstdint>
#include <stdint.h>
#include <math.h>

#define Bb 16
#define Tt 1024
#define Dd 512
#define Vv 5000
#define Vp 5120
#define Lc 128
#define Mm (Bb*Tt)
#define Sz (2*Lc+1)
#define NEGV (-1e30f)
#define NLAB 129

// scratch (static device allocations only)
__device__ float g_lse[Mm];
__device__ float g_lab[(size_t)Bb*Tt*NLAB];
__device__ float g_loss[Bb];
__device__ __nv_bfloat16 g_Hb[(size_t)Mm*Dd];
__device__ __nv_bfloat16 g_Wb[(size_t)Dd*Vp];

// ---------------------------------------------------------------------------
// helpers
// ---------------------------------------------------------------------------
__device__ __forceinline__ unsigned smaddr(const void* p)
{
    return (unsigned)__cvta_generic_to_shared(p);
}

__device__ __forceinline__ void ldsm4(unsigned* r, unsigned a)
{
    asm volatile("ldmatrix.sync.aligned.m8n8.x4.shared.b16 {%0,%1,%2,%3}, [%4];"
                 : "=r"(r[0]), "=r"(r[1]), "=r"(r[2]), "=r"(r[3])
                 : "r"(a));
}

__device__ __forceinline__ void ldsm4t(unsigned* r, unsigned a)
{
    asm volatile("ldmatrix.sync.aligned.m8n8.x4.trans.shared.b16 {%0,%1,%2,%3}, [%4];"
                 : "=r"(r[0]), "=r"(r[1]), "=r"(r[2]), "=r"(r[3])
                 : "r"(a));
}

__device__ __forceinline__ void mma16816(float* c, const unsigned* a,
                                         unsigned b0, unsigned b1)
{
    asm volatile("mma.sync.aligned.m16n8k16.row.col.f32.bf16.bf16.f32 {%0,%1,%2,%3},{%4,%5,%6,%7},{%8,%9},{%0,%1,%2,%3};"
                 : "+f"(c[0]), "+f"(c[1]), "+f"(c[2]), "+f"(c[3])
                 : "r"(a[0]), "r"(a[1]), "r"(a[2]), "r"(a[3]), "r"(b0), "r"(b1));
}

// ---------------------------------------------------------------------------
// Prep: fp32 -> bf16 conversions
// ---------------------------------------------------------------------------
__global__ void conv_h_kernel(const float* __restrict__ hs)
{
    int idx = blockIdx.x * blockDim.x + threadIdx.x;
    if (idx >= Mm * (Dd / 4)) {
        return;
    }
    int r = idx >> 7;
    int c4 = idx & 127;
    float4 v = *(const float4*)(hs + (size_t)r * Dd + c4 * 4);
    __nv_bfloat162 p0 = __floats2bfloat162_rn(v.x, v.y);
    __nv_bfloat162 p1 = __floats2bfloat162_rn(v.z, v.w);
    __nv_bfloat162* dst = (__nv_bfloat162*)(g_Hb + (size_t)r * Dd + c4 * 4);
    dst[0] = p0;
    dst[1] = p1;
}

__global__ void conv_w_kernel(const float* __restrict__ W)
{
    int idx = blockIdx.x * blockDim.x + threadIdx.x;
    if (idx >= Dd * (Vp / 4)) {
        return;
    }
    int r = idx / (Vp / 4);
    int c4 = idx % (Vp / 4);
    __nv_bfloat162 p0;
    __nv_bfloat162 p1;
    if (c4 < Vv / 4) {
        float4 v = *(const float4*)(W + (size_t)r * Vv + c4 * 4);
        p0 = __floats2bfloat162_rn(v.x, v.y);
        p1 = __floats2bfloat162_rn(v.z, v.w);
    } else {
        p0 = __floats2bfloat162_rn(0.f, 0.f);
        p1 = __floats2bfloat162_rn(0.f, 0.f);
    }
    __nv_bfloat162* dst = (__nv_bfloat162*)(g_Wb + (size_t)r * Vp + c4 * 4);
    dst[0] = p0;
    dst[1] = p1;
}

// ---------------------------------------------------------------------------
// Kernel A (tensor-core): fused GEMM H[16384x512] x W[512x5120] (bf16, f32 acc)
// with online row-wise logsumexp. BM=128, BN=128, BK=64, 256 threads.
// ---------------------------------------------------------------------------
__global__ __launch_bounds__(256, 1) void lse_mma_kernel(
    const float* __restrict__ bias)
{
    __shared__ __align__(16) __nv_bfloat16 sA[128][72];    // stride 144B (bank-offset 4)
    __shared__ __align__(16) __nv_bfloat16 sBt[64][136];   // stride 272B (bank-offset 4)
    __shared__ float sBias[128];
    __shared__ float sM[2][128];
    __shared__ float sS[2][128];

    const int mblk = blockIdx.x * 128;
    const int tid  = threadIdx.x;
    const int lane = tid & 31;
    const int wid  = tid >> 5;
    const int wm   = wid & 3;       // warp row 0..3 -> rows wm*32..+31
    const int wn   = wid >> 2;      // warp col 0..1 -> cols wn*64..+63

    float Mr[2][2];
    float Sr[2][2];
    for (int mt = 0; mt < 2; mt++) {
        for (int h = 0; h < 2; h++) {
            Mr[mt][h] = NEGV;
            Sr[mt][h] = 0.f;
        }
    }

    const int ra = tid >> 3;        // A load row (per 16B vec), +32 per q
    const int ca = tid & 7;
    const int rb = tid >> 4;        // B load row, +16 per q
    const int cb = tid & 15;

    uint4 pa[4];
    uint4 pb[4];

    for (int nt = 0; nt < Vp / 128; nt++) {
        const int n0 = nt * 128;
        __syncthreads();            // previous epilogue done with smem
        if (tid < 128) {
            int n = n0 + tid;
            sBias[tid] = (n < Vv) ? bias[n] : NEGV;
        }

        float acc[2][8][4];
        for (int mt = 0; mt < 2; mt++) {
            for (int j = 0; j < 8; j++) {
                for (int e = 0; e < 4; e++) {
                    acc[mt][j][e] = 0.f;
                }
            }
        }

        // prefetch kt=0
        #pragma unroll
        for (int q = 0; q < 4; q++) {
            pa[q] = *(const uint4*)(g_Hb + (size_t)(mblk + ra + q * 32) * Dd + ca * 8);
            pb[q] = *(const uint4*)(g_Wb + (size_t)(rb + q * 16) * Vp + n0 + cb * 8);
        }

        for (int kt = 0; kt < Dd / 64; kt++) {
            __syncthreads();
            #pragma unroll
            for (int q = 0; q < 4; q++) {
                *(uint4*)(&sA[ra + q * 32][ca * 8]) = pa[q];
                *(uint4*)(&sBt[rb + q * 16][cb * 8]) = pb[q];
            }
            __syncthreads();
            if (kt + 1 < Dd / 64) {
                const int k0n = (kt + 1) * 64;
                #pragma unroll
                for (int q = 0; q < 4; q++) {
                    pa[q] = *(const uint4*)(g_Hb + (size_t)(mblk + ra + q * 32) * Dd + k0n + ca * 8);
                    pb[q] = *(const uint4*)(g_Wb + (size_t)(k0n + rb + q * 16) * Vp + n0 + cb * 8);
                }
            }
            #pragma unroll
            for (int ks = 0; ks < 4; ks++) {
                const int k0 = ks * 16;
                unsigned afr[2][4];
                #pragma unroll
                for (int mt = 0; mt < 2; mt++) {
                    int row = wm * 32 + mt * 16 + (lane & 15);
                    int col = k0 + 8 * (lane >> 4);
                    ldsm4(afr[mt], smaddr(&sA[row][col]));
                }
                unsigned bfr[4][4];
                #pragma unroll
                for (int np = 0; np < 4; np++) {
                    int rk = k0 + (lane & 15);
                    int cn = wn * 64 + np * 16 + 8 * (lane >> 4);
                    ldsm4t(bfr[np], smaddr(&sBt[rk][cn]));
                }
                #pragma unroll
                for (int mt = 0; mt < 2; mt++) {
                    #pragma unroll
                    for (int np = 0; np < 4; np++) {
                        mma16816(acc[mt][2 * np + 0], afr[mt], bfr[np][0], bfr[np][1]);
                        mma16816(acc[mt][2 * np + 1], afr[mt], bfr[np][2], bfr[np][3]);
                    }
                }
            }
        }

        // online (max,sumexp) update for this N tile
        #pragma unroll
        for (int mt = 0; mt < 2; mt++) {
            #pragma unroll
            for (int h = 0; h < 2; h++) {
                float vals[16];
                float vm = NEGV;
                #pragma unroll
                for (int np = 0; np < 8; np++) {
                    int nb = wn * 64 + np * 8 + (lane & 3) * 2;
                    float x0 = acc[mt][np][h * 2 + 0] + sBias[nb];
                    float x1 = acc[mt][np][h * 2 + 1] + sBias[nb + 1];
                    vals[np * 2 + 0] = x0;
                    vals[np * 2 + 1] = x1;
                    vm = fmaxf(vm, fmaxf(x0, x1));
                }
                float M0 = Mr[mt][h];
                float nM = fmaxf(M0, vm);
                float s  = Sr[mt][h] * __expf(M0 - nM);
                #pragma unroll
                for (int j = 0; j < 16; j++) {
                    s += __expf(vals[j] - nM);
                }
                Mr[mt][h] = nM;
                Sr[mt][h] = s;
            }
        }
    }

    // combine across the 4 lanes sharing a row, then across the 2 n-warps
    #pragma unroll
    for (int mt = 0; mt < 2; mt++) {
        #pragma unroll
        for (int h = 0; h < 2; h++) {
            float m = Mr[mt][h];
            float s = Sr[mt][h];
            #pragma unroll
            for (int off = 1; off <= 2; off <<= 1) {
                float om = __shfl_xor_sync(0xffffffffu, m, off);
                float os = __shfl_xor_sync(0xffffffffu, s, off);
                float nm = fmaxf(m, om);
                s = s * __expf(m - nm) + os * __expf(om - nm);
                m = nm;
            }
            if ((lane & 3) == 0) {
                int row = wm * 32 + mt * 16 + h * 8 + (lane >> 2);
                sM[wn][row] = m;
                sS[wn][row] = s;
            }
        }
    }
    __syncthreads();
    if (tid < 128) {
        float m0 = sM[0][tid];
        float s0 = sS[0][tid];
        float m1 = sM[1][tid];
        float s1 = sS[1][tid];
        float nm = fmaxf(m0, m1);
        float s  = s0 * __expf(m0 - nm) + s1 * __expf(m1 - nm);
        g_lse[mblk + tid] = nm + logf(s);
    }
}

// ---------------------------------------------------------------------------
// Kernel B: gathered-label logits -> log-probs. (unchanged from R5)
// ---------------------------------------------------------------------------
__global__ __launch_bounds__(256) void lab_kernel(
    const float* __restrict__ hs, const float* __restrict__ W,
    const float* __restrict__ bias, const int* __restrict__ ys)
{
    __shared__ float sH[16][64];
    __shared__ float sWg[16][144];
    __shared__ float sBg[144];
    __shared__ int   sV[144];

    const int b   = blockIdx.y;
    const int t0  = blockIdx.x * 64;
    const int tid = threadIdx.x;
    const int ty  = tid >> 4;
    const int tx  = tid & 15;

    if (tid < 144) {
        int v = 0;
        if (tid >= 1 && tid < NLAB) {
            v = ys[b * Lc + tid - 1];
        }
        sV[tid]  = v;
        sBg[tid] = (tid < NLAB) ? bias[v] : 0.f;
    }
    __syncthreads();

    float acc[4][9];
    for (int i = 0; i < 4; i++) {
        for (int c = 0; c < 9; c++) {
            acc[i][c] = 0.f;
        }
    }

    for (int kt = 0; kt < 32; kt++) {
        const int k0 = kt * 16;
        {
            int mrow = tid >> 2;
            int k4 = tid & 3;
            float4 h = *(const float4*)(hs + (size_t)(b * Tt + t0 + mrow) * Dd + k0 + k4 * 4);
            sH[k4 * 4 + 0][mrow] = h.x;
            sH[k4 * 4 + 1][mrow] = h.y;
            sH[k4 * 4 + 2][mrow] = h.z;
            sH[k4 * 4 + 3][mrow] = h.w;
        }
        for (int idx = tid; idx < 16 * 144; idx += 256) {
            int kr = idx / 144;
            int j = idx % 144;
            sWg[kr][j] = (j < NLAB) ? W[(size_t)(k0 + kr) * Vv + sV[j]] : 0.f;
        }
        __syncthreads();
        #pragma unroll
        for (int kk = 0; kk < 16; kk++) {
            float a[4];
            float w[9];
            #pragma unroll
            for (int i = 0; i < 4; i++) {
                a[i] = sH[kk][ty * 4 + i];
            }
            #pragma unroll
            for (int c = 0; c < 9; c++) {
                w[c] = sWg[kk][tx + 16 * c];
            }
            #pragma unroll
            for (int i = 0; i < 4; i++) {
                #pragma unroll
                for (int c = 0; c < 9; c++) {
                    acc[i][c] = fmaf(a[i], w[c], acc[i][c]);
                }
            }
        }
        __syncthreads();
    }

    for (int i = 0; i < 4; i++) {
        int m = b * Tt + t0 + ty * 4 + i;
        float lse = g_lse[m];
        for (int c = 0; c < 9; c++) {
            int j = tx + 16 * c;
            if (j < NLAB) {
                g_lab[(size_t)m * NLAB + j] = acc[i][c] + sBg[j] - lse;
            }
        }
    }
}

// ---------------------------------------------------------------------------
// Kernel C: CTC alpha recursion. (unchanged from R5)
// ---------------------------------------------------------------------------
__global__ __launch_bounds__(288) void ctc_kernel(
    const int* __restrict__ hlens, const int* __restrict__ ys,
    const int* __restrict__ yslens)
{
    __shared__ float A0[Sz];
    __shared__ float A1[Sz];

    const int b   = blockIdx.x;
    const int tid = threadIdx.x;
    const int hlen = hlens[b];
    const float* lp = g_lab + (size_t)b * Tt * NLAB;

    int  labj  = 0;
    bool allow = false;
    if (tid < Sz) {
        if (tid & 1) {
            labj = (tid + 1) >> 1;
            int y     = ys[b * Lc + labj - 1];
            int yprev = (tid >= 3) ? ys[b * Lc + labj - 2] : -1;
            allow = (y != yprev);
        }
        float a0 = NEGV;
        if (tid == 0) {
            a0 = lp[0];
        }
        if (tid == 1) {
            a0 = lp[1];
        }
        A0[tid] = a0;
    }
    __syncthreads();

    float lp_cur = 0.f;
    float lp_nxt = 0.f;
    if (tid < Sz) {
        lp_cur = lp[(size_t)1 * NLAB + labj];
    }

    float* cur = A0;
    float* nxt = A1;
    for (int t = 1; t < hlen; t++) {
        if (tid < Sz) {
            int tl = (t + 1 < Tt) ? (t + 1) : (Tt - 1);
            lp_nxt = lp[(size_t)tl * NLAB + labj];
            float a1 = cur[tid];
            float a2 = (tid >= 1) ? cur[tid - 1] : NEGV;
            float a3 = (allow && tid >= 2) ? cur[tid - 2] : NEGV;
            float m  = fmaxf(fmaxf(a1, a2), a3);
            m = fmaxf(m, NEGV);
            float s = __expf(a1 - m) + __expf(a2 - m) + __expf(a3 - m);
            nxt[tid] = m + __logf(s) + lp_cur;
        }
        __syncthreads();
        lp_cur = lp_nxt;
        float* tmp = cur;
        cur = nxt;
        nxt = tmp;
    }

    if (tid == 0) {
        int yl = yslens[b];
        int i1 = 2 * yl;
        int i2 = (i1 - 1 > 0) ? (i1 - 1) : 0;
        float a = cur[i1];
        float c2 = cur[i2];
        float m = fmaxf(a, c2);
        float ll = m + __logf(__expf(a - m) + __expf(c2 - m));
        float loss = -ll;
        if (!isfinite(loss) || loss >= 1e29f) {
            loss = 0.f;
        }
        g_loss[b] = loss;
    }
}

// ---------------------------------------------------------------------------
// Kernel D: final reduction + normalization.
// ---------------------------------------------------------------------------
__global__ void final_kernel(const int* __restrict__ yslens, float* __restrict__ out)
{
    if (threadIdx.x == 0) {
        float s = 0.f;
        int tl = 0;
        for (int i = 0; i < Bb; i++) {
            s += g_loss[i];
            tl += yslens[i];
        }
        out[0] = s / (float)tl;
    }
}

extern "C" void kernel_launch(void* const* d_in, const int* in_sizes, int n_in,
                              void* d_out, int out_size)
{
    const float* hs     = (const float*)d_in[0];
    const int*   hlens  = (const int*)  d_in[1];
    const int*   ys     = (const int*)  d_in[2];
    const int*   yslens = (const int*)  d_in[3];
    const float* W      = (const float*)d_in[4];
    const float* bias   = (const float*)d_in[5];

    conv_h_kernel<<<(Mm * (Dd / 4) + 255) / 256, 256>>>(hs);
    conv_w_kernel<<<(Dd * (Vp / 4) + 255) / 256, 256>>>(W);
    lse_mma_kernel<<<Mm / 128, 256>>>(bias);
    dim3 gb(Tt / 64, Bb);
    lab_kernel<<<gb, 256>>>(hs, W, bias, ys);
    ctc_kernel<<<Bb, 288>>>(hlens, ys, yslens);
    final_kernel<<<1, 32>>>(yslens, (float*)d_out);
}

// round 11
// speedup vs baseline: 6.0715x; 1.1622x over previous
#include <cuda_runtime.h>
#include <cuda_bf16.h>
#include <cstdint>
#include <stdint.h>
#include <math.h>

#define Bb 16
#define Tt 1024
#define Dd 512
#define Vv 5000
#define Vp 5120
#define Lc 128
#define Mm (Bb*Tt)
#define Sz (2*Lc+1)
#define NEGV (-1e30f)
#define NLAB 129
#define JP 160              // NLAB padded for MMA tiling

// scratch (static device allocations only)
__device__ float g_lse[Mm];
__device__ float g_lab[(size_t)Bb*Tt*NLAB];
__device__ float g_loss[Bb];
__device__ __nv_bfloat16 g_Hb[(size_t)Mm*Dd];
__device__ __nv_bfloat16 g_Wb[(size_t)Dd*Vp];
__device__ __nv_bfloat16 g_Wg[(size_t)Bb*Dd*JP];   // gathered label columns (dense)
__device__ float g_bg[Bb][JP];                     // gathered bias

// ---------------------------------------------------------------------------
// helpers
// ---------------------------------------------------------------------------
__device__ __forceinline__ unsigned smaddr(const void* p)
{
    return (unsigned)__cvta_generic_to_shared(p);
}

__device__ __forceinline__ void ldsm4(unsigned* r, unsigned a)
{
    asm volatile("ldmatrix.sync.aligned.m8n8.x4.shared.b16 {%0,%1,%2,%3}, [%4];"
                 : "=r"(r[0]), "=r"(r[1]), "=r"(r[2]), "=r"(r[3])
                 : "r"(a));
}

__device__ __forceinline__ void ldsm4t(unsigned* r, unsigned a)
{
    asm volatile("ldmatrix.sync.aligned.m8n8.x4.trans.shared.b16 {%0,%1,%2,%3}, [%4];"
                 : "=r"(r[0]), "=r"(r[1]), "=r"(r[2]), "=r"(r[3])
                 : "r"(a));
}

__device__ __forceinline__ void mma16816(float* c, const unsigned* a,
                                         unsigned b0, unsigned b1)
{
    asm volatile("mma.sync.aligned.m16n8k16.row.col.f32.bf16.bf16.f32 {%0,%1,%2,%3},{%4,%5,%6,%7},{%8,%9},{%0,%1,%2,%3};"
                 : "+f"(c[0]), "+f"(c[1]), "+f"(c[2]), "+f"(c[3])
                 : "r"(a[0]), "r"(a[1]), "r"(a[2]), "r"(a[3]), "r"(b0), "r"(b1));
}

// ---------------------------------------------------------------------------
// Prep: fp32 -> bf16 conversions
// ---------------------------------------------------------------------------
__global__ void conv_h_kernel(const float* __restrict__ hs)
{
    int idx = blockIdx.x * blockDim.x + threadIdx.x;
    if (idx >= Mm * (Dd / 4)) {
        return;
    }
    int r = idx >> 7;
    int c4 = idx & 127;
    float4 v = *(const float4*)(hs + (size_t)r * Dd + c4 * 4);
    __nv_bfloat162 p0 = __floats2bfloat162_rn(v.x, v.y);
    __nv_bfloat162 p1 = __floats2bfloat162_rn(v.z, v.w);
    __nv_bfloat162* dst = (__nv_bfloat162*)(g_Hb + (size_t)r * Dd + c4 * 4);
    dst[0] = p0;
    dst[1] = p1;
}

__global__ void conv_w_kernel(const float* __restrict__ W)
{
    int idx = blockIdx.x * blockDim.x + threadIdx.x;
    if (idx >= Dd * (Vp / 4)) {
        return;
    }
    int r = idx / (Vp / 4);
    int c4 = idx % (Vp / 4);
    __nv_bfloat162 p0;
    __nv_bfloat162 p1;
    if (c4 < Vv / 4) {
        float4 v = *(const float4*)(W + (size_t)r * Vv + c4 * 4);
        p0 = __floats2bfloat162_rn(v.x, v.y);
        p1 = __floats2bfloat162_rn(v.z, v.w);
    } else {
        p0 = __floats2bfloat162_rn(0.f, 0.f);
        p1 = __floats2bfloat162_rn(0.f, 0.f);
    }
    __nv_bfloat162* dst = (__nv_bfloat162*)(g_Wb + (size_t)r * Vp + c4 * 4);
    dst[0] = p0;
    dst[1] = p1;
}

// ---------------------------------------------------------------------------
// Gather label columns of W (bf16) into dense g_Wg[b][512][JP] once.
// grid (8 k-slabs of 64, Bb), 256 threads.
// ---------------------------------------------------------------------------
__global__ void gather_w_kernel(const float* __restrict__ bias,
                                const int* __restrict__ ys)
{
    __shared__ int sV[JP];

    const int b   = blockIdx.y;
    const int k0  = blockIdx.x * 64;
    const int tid = threadIdx.x;

    if (tid < JP) {
        int v = -1;
        if (tid == 0) {
            v = 0;                               // blank
        } else if (tid < NLAB) {
            v = ys[b * Lc + tid - 1];
        }
        sV[tid] = v;
        if (blockIdx.x == 0) {
            g_bg[b][tid] = (v >= 0) ? bias[v] : 0.f;
        }
    }
    __syncthreads();

    for (int idx = tid; idx < 64 * JP; idx += 256) {
        int k = idx / JP;
        int j = idx % JP;
        int v = sV[j];
        __nv_bfloat16 w = __float2bfloat16(0.f);
        if (v >= 0) {
            w = g_Wb[(size_t)(k0 + k) * Vp + v];
        }
        g_Wg[((size_t)b * Dd + k0 + k) * JP + j] = w;
    }
}

// ---------------------------------------------------------------------------
// Kernel A (tensor-core): fused GEMM H[16384x512] x W[512x5120] (bf16, f32 acc)
// with online row-wise logsumexp. BM=128, BN=128, BK=64, 256 threads.
// ---------------------------------------------------------------------------
__global__ __launch_bounds__(256, 1) void lse_mma_kernel(
    const float* __restrict__ bias)
{
    __shared__ __align__(16) __nv_bfloat16 sA[128][72];
    __shared__ __align__(16) __nv_bfloat16 sBt[64][136];
    __shared__ float sBias[128];
    __shared__ float sM[2][128];
    __shared__ float sS[2][128];

    const int mblk = blockIdx.x * 128;
    const int tid  = threadIdx.x;
    const int lane = tid & 31;
    const int wid  = tid >> 5;
    const int wm   = wid & 3;
    const int wn   = wid >> 2;

    float Mr[2][2];
    float Sr[2][2];
    for (int mt = 0; mt < 2; mt++) {
        for (int h = 0; h < 2; h++) {
            Mr[mt][h] = NEGV;
            Sr[mt][h] = 0.f;
        }
    }

    const int ra = tid >> 3;
    const int ca = tid & 7;
    const int rb = tid >> 4;
    const int cb = tid & 15;

    uint4 pa[4];
    uint4 pb[4];

    for (int nt = 0; nt < Vp / 128; nt++) {
        const int n0 = nt * 128;
        __syncthreads();
        if (tid < 128) {
            int n = n0 + tid;
            sBias[tid] = (n < Vv) ? bias[n] : NEGV;
        }

        float acc[2][8][4];
        for (int mt = 0; mt < 2; mt++) {
            for (int j = 0; j < 8; j++) {
                for (int e = 0; e < 4; e++) {
                    acc[mt][j][e] = 0.f;
                }
            }
        }

        #pragma unroll
        for (int q = 0; q < 4; q++) {
            pa[q] = *(const uint4*)(g_Hb + (size_t)(mblk + ra + q * 32) * Dd + ca * 8);
            pb[q] = *(const uint4*)(g_Wb + (size_t)(rb + q * 16) * Vp + n0 + cb * 8);
        }

        for (int kt = 0; kt < Dd / 64; kt++) {
            __syncthreads();
            #pragma unroll
            for (int q = 0; q < 4; q++) {
                *(uint4*)(&sA[ra + q * 32][ca * 8]) = pa[q];
                *(uint4*)(&sBt[rb + q * 16][cb * 8]) = pb[q];
            }
            __syncthreads();
            if (kt + 1 < Dd / 64) {
                const int k0n = (kt + 1) * 64;
                #pragma unroll
                for (int q = 0; q < 4; q++) {
                    pa[q] = *(const uint4*)(g_Hb + (size_t)(mblk + ra + q * 32) * Dd + k0n + ca * 8);
                    pb[q] = *(const uint4*)(g_Wb + (size_t)(k0n + rb + q * 16) * Vp + n0 + cb * 8);
                }
            }
            #pragma unroll
            for (int ks = 0; ks < 4; ks++) {
                const int k0 = ks * 16;
                unsigned afr[2][4];
                #pragma unroll
                for (int mt = 0; mt < 2; mt++) {
                    int row = wm * 32 + mt * 16 + (lane & 15);
                    int col = k0 + 8 * (lane >> 4);
                    ldsm4(afr[mt], smaddr(&sA[row][col]));
                }
                unsigned bfr[4][4];
                #pragma unroll
                for (int np = 0; np < 4; np++) {
                    int rk = k0 + (lane & 15);
                    int cn = wn * 64 + np * 16 + 8 * (lane >> 4);
                    ldsm4t(bfr[np], smaddr(&sBt[rk][cn]));
                }
                #pragma unroll
                for (int mt = 0; mt < 2; mt++) {
                    #pragma unroll
                    for (int np = 0; np < 4; np++) {
                        mma16816(acc[mt][2 * np + 0], afr[mt], bfr[np][0], bfr[np][1]);
                        mma16816(acc[mt][2 * np + 1], afr[mt], bfr[np][2], bfr[np][3]);
                    }
                }
            }
        }

        #pragma unroll
        for (int mt = 0; mt < 2; mt++) {
            #pragma unroll
            for (int h = 0; h < 2; h++) {
                float vals[16];
                float vm = NEGV;
                #pragma unroll
                for (int np = 0; np < 8; np++) {
                    int nb = wn * 64 + np * 8 + (lane & 3) * 2;
                    float x0 = acc[mt][np][h * 2 + 0] + sBias[nb];
                    float x1 = acc[mt][np][h * 2 + 1] + sBias[nb + 1];
                    vals[np * 2 + 0] = x0;
                    vals[np * 2 + 1] = x1;
                    vm = fmaxf(vm, fmaxf(x0, x1));
                }
                float M0 = Mr[mt][h];
                float nM = fmaxf(M0, vm);
                float s  = Sr[mt][h] * __expf(M0 - nM);
                #pragma unroll
                for (int j = 0; j < 16; j++) {
                    s += __expf(vals[j] - nM);
                }
                Mr[mt][h] = nM;
                Sr[mt][h] = s;
            }
        }
    }

    #pragma unroll
    for (int mt = 0; mt < 2; mt++) {
        #pragma unroll
        for (int h = 0; h < 2; h++) {
            float m = Mr[mt][h];
            float s = Sr[mt][h];
            #pragma unroll
            for (int off = 1; off <= 2; off <<= 1) {
                float om = __shfl_xor_sync(0xffffffffu, m, off);
                float os = __shfl_xor_sync(0xffffffffu, s, off);
                float nm = fmaxf(m, om);
                s = s * __expf(m - nm) + os * __expf(om - nm);
                m = nm;
            }
            if ((lane & 3) == 0) {
                int row = wm * 32 + mt * 16 + h * 8 + (lane >> 2);
                sM[wn][row] = m;
                sS[wn][row] = s;
            }
        }
    }
    __syncthreads();
    if (tid < 128) {
        float m0 = sM[0][tid];
        float s0 = sS[0][tid];
        float m1 = sM[1][tid];
        float s1 = sS[1][tid];
        float nm = fmaxf(m0, m1);
        float s  = s0 * __expf(m0 - nm) + s1 * __expf(m1 - nm);
        g_lse[mblk + tid] = nm + logf(s);
    }
}

// ---------------------------------------------------------------------------
// Kernel B (tensor-core): dense label-GEMM 128x160x512 per block.
// grid (Tt/128, Bb), 256 threads (8 warps: 4m x 2n), warp tile 32x80.
// ---------------------------------------------------------------------------
__global__ __launch_bounds__(256, 1) void lab_mma_kernel()
{
    __shared__ __align__(16) __nv_bfloat16 sA[128][72];
    __shared__ __align__(16) __nv_bfloat16 sBt[64][168];
    __shared__ float sBg[JP];

    const int b    = blockIdx.y;
    const int t0   = blockIdx.x * 128;
    const int tid  = threadIdx.x;
    const int lane = tid & 31;
    const int wid  = tid >> 5;
    const int wm   = wid & 3;       // rows wm*32..+31
    const int wn   = wid >> 2;      // cols wn*80..+79

    if (tid < JP) {
        sBg[tid] = g_bg[b][tid];
    }

    const __nv_bfloat16* Aptr = g_Hb + (size_t)(b * Tt + t0) * Dd;
    const __nv_bfloat16* Bptr = g_Wg + (size_t)b * Dd * JP;

    float acc[2][10][4];
    for (int mt = 0; mt < 2; mt++) {
        for (int j = 0; j < 10; j++) {
            for (int e = 0; e < 4; e++) {
                acc[mt][j][e] = 0.f;
            }
        }
    }

    const int ra = tid >> 3;    // A: row ra + q*32, col ca*8
    const int ca = tid & 7;

    uint4 pa[4];
    uint4 pb[5];

    // prefetch kt=0
    #pragma unroll
    for (int q = 0; q < 4; q++) {
        pa[q] = *(const uint4*)(Aptr + (size_t)(ra + q * 32) * Dd + ca * 8);
    }
    #pragma unroll
    for (int q = 0; q < 5; q++) {
        int idx = q * 256 + tid;
        int r = idx / 20;           // 64 rows x 20 uint4/row
        int c = idx % 20;
        pb[q] = *(const uint4*)(Bptr + (size_t)r * JP + c * 8);
    }

    for (int kt = 0; kt < Dd / 64; kt++) {
        __syncthreads();
        #pragma unroll
        for (int q = 0; q < 4; q++) {
            *(uint4*)(&sA[ra + q * 32][ca * 8]) = pa[q];
        }
        #pragma unroll
        for (int q = 0; q < 5; q++) {
            int idx = q * 256 + tid;
            int r = idx / 20;
            int c = idx % 20;
            *(uint4*)(&sBt[r][c * 8]) = pb[q];
        }
        __syncthreads();
        if (kt + 1 < Dd / 64) {
            const int k0n = (kt + 1) * 64;
            #pragma unroll
            for (int q = 0; q < 4; q++) {
                pa[q] = *(const uint4*)(Aptr + (size_t)(ra + q * 32) * Dd + k0n + ca * 8);
            }
            #pragma unroll
            for (int q = 0; q < 5; q++) {
                int idx = q * 256 + tid;
                int r = idx / 20;
                int c = idx % 20;
                pb[q] = *(const uint4*)(Bptr + (size_t)(k0n + r) * JP + c * 8);
            }
        }
        #pragma unroll
        for (int ks = 0; ks < 4; ks++) {
            const int k0 = ks * 16;
            unsigned afr[2][4];
            #pragma unroll
            for (int mt = 0; mt < 2; mt++) {
                int row = wm * 32 + mt * 16 + (lane & 15);
                int col = k0 + 8 * (lane >> 4);
                ldsm4(afr[mt], smaddr(&sA[row][col]));
            }
            unsigned bfr[5][4];
            #pragma unroll
            for (int np = 0; np < 5; np++) {
                int rk = k0 + (lane & 15);
                int cn = wn * 80 + np * 16 + 8 * (lane >> 4);
                ldsm4t(bfr[np], smaddr(&sBt[rk][cn]));
            }
            #pragma unroll
            for (int mt = 0; mt < 2; mt++) {
                #pragma unroll
                for (int np = 0; np < 5; np++) {
                    mma16816(acc[mt][2 * np + 0], afr[mt], bfr[np][0], bfr[np][1]);
                    mma16816(acc[mt][2 * np + 1], afr[mt], bfr[np][2], bfr[np][3]);
                }
            }
        }
    }

    // epilogue: g_lab[m][j] = logit + bias_g - lse
    #pragma unroll
    for (int mt = 0; mt < 2; mt++) {
        int r0 = wm * 32 + mt * 16 + (lane >> 2);
        int r1 = r0 + 8;
        int m0 = b * Tt + t0 + r0;
        int m1 = b * Tt + t0 + r1;
        float lse0 = g_lse[m0];
        float lse1 = g_lse[m1];
        #pragma unroll
        for (int np = 0; np < 5; np++) {
            #pragma unroll
            for (int h = 0; h < 2; h++) {
                int j = wn * 80 + np * 16 + h * 8 + (lane & 3) * 2;
                float* a = acc[mt][2 * np + h];
                if (j < NLAB) {
                    g_lab[(size_t)m0 * NLAB + j] = a[0] + sBg[j] - lse0;
                    g_lab[(size_t)m1 * NLAB + j] = a[2] + sBg[j] - lse1;
                }
                if (j + 1 < NLAB) {
                    g_lab[(size_t)m0 * NLAB + j + 1] = a[1] + sBg[j + 1] - lse0;
                    g_lab[(size_t)m1 * NLAB + j + 1] = a[3] + sBg[j + 1] - lse1;
                }
            }
        }
    }
}

// ---------------------------------------------------------------------------
// Kernel C: CTC alpha recursion.
// ---------------------------------------------------------------------------
__global__ __launch_bounds__(288) void ctc_kernel(
    const int* __restrict__ hlens, const int* __restrict__ ys,
    const int* __restrict__ yslens)
{
    __shared__ float A0[Sz];
    __shared__ float A1[Sz];

    const int b   = blockIdx.x;
    const int tid = threadIdx.x;
    const int hlen = hlens[b];
    const float* lp = g_lab + (size_t)b * Tt * NLAB;

    int  labj  = 0;
    bool allow = false;
    if (tid < Sz) {
        if (tid & 1) {
            labj = (tid + 1) >> 1;
            int y     = ys[b * Lc + labj - 1];
            int yprev = (tid >= 3) ? ys[b * Lc + labj - 2] : -1;
            allow = (y != yprev);
        }
        float a0 = NEGV;
        if (tid == 0) {
            a0 = lp[0];
        }
        if (tid == 1) {
            a0 = lp[1];
        }
        A0[tid] = a0;
    }
    __syncthreads();

    float lp_cur = 0.f;
    float lp_nxt = 0.f;
    if (tid < Sz) {
        lp_cur = lp[(size_t)1 * NLAB + labj];
    }

    float* cur = A0;
    float* nxt = A1;
    for (int t = 1; t < hlen; t++) {
        if (tid < Sz) {
            int tl = (t + 1 < Tt) ? (t + 1) : (Tt - 1);
            lp_nxt = lp[(size_t)tl * NLAB + labj];
            float a1 = cur[tid];
            float a2 = (tid >= 1) ? cur[tid - 1] : NEGV;
            float a3 = (allow && tid >= 2) ? cur[tid - 2] : NEGV;
            float m  = fmaxf(fmaxf(a1, a2), a3);
            m = fmaxf(m, NEGV);
            float s = __expf(a1 - m) + __expf(a2 - m) + __expf(a3 - m);
            nxt[tid] = m + __logf(s) + lp_cur;
        }
        __syncthreads();
        lp_cur = lp_nxt;
        float* tmp = cur;
        cur = nxt;
        nxt = tmp;
    }

    if (tid == 0) {
        int yl = yslens[b];
        int i1 = 2 * yl;
        int i2 = (i1 - 1 > 0) ? (i1 - 1) : 0;
        float a = cur[i1];
        float c2 = cur[i2];
        float m = fmaxf(a, c2);
        float ll = m + __logf(__expf(a - m) + __expf(c2 - m));
        float loss = -ll;
        if (!isfinite(loss) || loss >= 1e29f) {
            loss = 0.f;
        }
        g_loss[b] = loss;
    }
}

// ---------------------------------------------------------------------------
// Kernel D: final reduction + normalization.
// ---------------------------------------------------------------------------
__global__ void final_kernel(const int* __restrict__ yslens, float* __restrict__ out)
{
    if (threadIdx.x == 0) {
        float s = 0.f;
        int tl = 0;
        for (int i = 0; i < Bb; i++) {
            s += g_loss[i];
            tl += yslens[i];
        }
        out[0] = s / (float)tl;
    }
}

extern "C" void kernel_launch(void* const* d_in, const int* in_sizes, int n_in,
                              void* d_out, int out_size)
{
    const float* hs     = (const float*)d_in[0];
    const int*   hlens  = (const int*)  d_in[1];
    const int*   ys     = (const int*)  d_in[2];
    const int*   yslens = (const int*)  d_in[3];
    const float* W      = (const float*)d_in[4];
    const float* bias   = (const float*)d_in[5];

    conv_h_kernel<<<(Mm * (Dd / 4) + 255) / 256, 256>>>(hs);
    conv_w_kernel<<<(Dd * (Vp / 4) + 255) / 256, 256>>>(W);
    dim3 gg(Dd / 64, Bb);
    gather_w_kernel<<<gg, 256>>>(bias, ys);
    lse_mma_kernel<<<Mm / 128, 256>>>(bias);
    dim3 gb(Tt / 128, Bb);
    lab_mma_kernel<<<gb, 256>>>();
    ctc_kernel<<<Bb, 288>>>(hlens, ys, yslens);
    final_kernel<<<1, 32>>>(yslens, (float*)d_out);
}